// round 1
// baseline (speedup 1.0000x reference)
#include <cuda_runtime.h>

// InterpolatorMask: out = valid ? sum_j mask[j] * y[(j + ind) % N] : 0
//   ind  = floor((x - x0)/dx), x0 = xOrig[0], dx = xOrig[1]-xOrig[0], xMax = xOrig[N-1]
//
// Inputs (metadata order): d_in[0]=x (1 float), d_in[1]=xOrig (N), d_in[2]=yOrig (N), d_in[3]=mask (N)
// Output: 1 float scalar.
//
// Strategy: stream mask with float4 loads (coalesced, 64 MB); gather y only where
// mask != 0 (mask is ~all zeros). Warp-ballot skips all-zero warps; rare nonzero
// warps reduce via shfl and atomicAdd into the scalar output.

__global__ void im_init_out(float* __restrict__ out) {
    if (blockIdx.x == 0 && threadIdx.x == 0) out[0] = 0.0f;
}

__global__ void __launch_bounds__(256) im_kernel(
    const float* __restrict__ xp,
    const float* __restrict__ xOrig,
    const float* __restrict__ y,
    const float* __restrict__ mask,
    float* __restrict__ out,
    int n)
{
    const unsigned tid = blockIdx.x * blockDim.x + threadIdx.x;   // one float4 per thread
    const float4 m = reinterpret_cast<const float4*>(mask)[tid];

    float sum = 0.0f;
    const bool any = (m.x != 0.0f) | (m.y != 0.0f) | (m.z != 0.0f) | (m.w != 0.0f);

    if (any) {
        // Only the (rare) nonzero threads pay for these scalar loads (L2/L1 cached).
        const float x    = xp[0];
        const float x0   = xOrig[0];
        const float dx   = xOrig[1] - x0;
        const int   ind  = (int)floorf((x - x0) / dx);

        int j = (int)(tid * 4u);
        int i0 = j + 0 + ind; if (i0 >= n) i0 -= n;
        int i1 = j + 1 + ind; if (i1 >= n) i1 -= n;
        int i2 = j + 2 + ind; if (i2 >= n) i2 -= n;
        int i3 = j + 3 + ind; if (i3 >= n) i3 -= n;

        if (m.x != 0.0f) sum += m.x * y[i0];
        if (m.y != 0.0f) sum += m.y * y[i1];
        if (m.z != 0.0f) sum += m.z * y[i2];
        if (m.w != 0.0f) sum += m.w * y[i3];
    }

    // Skip entirely-zero warps (the overwhelmingly common case).
    const unsigned act = __ballot_sync(0xffffffffu, sum != 0.0f);
    if (act != 0u) {
        // Warp reduction (all 32 lanes participate).
        #pragma unroll
        for (int o = 16; o > 0; o >>= 1)
            sum += __shfl_down_sync(0xffffffffu, sum, o);

        if ((threadIdx.x & 31u) == 0u && sum != 0.0f) {
            const float x    = xp[0];
            const float x0   = xOrig[0];
            const float xMax = xOrig[n - 1];
            const bool valid = (x >= x0) && (x < xMax);
            if (valid) atomicAdd(out, sum);
        }
    }
}

extern "C" void kernel_launch(void* const* d_in, const int* in_sizes, int n_in,
                              void* d_out, int out_size)
{
    const float* x     = (const float*)d_in[0];
    const float* xOrig = (const float*)d_in[1];
    const float* y     = (const float*)d_in[2];
    const float* mask  = (const float*)d_in[3];
    float* out = (float*)d_out;

    const int n = in_sizes[1];              // 16,777,216
    const int threads = 256;
    const int vec = n / 4;                  // float4 elements
    const int blocks = (vec + threads - 1) / threads;   // 16384

    im_init_out<<<1, 32>>>(out);
    im_kernel<<<blocks, threads>>>(x, xOrig, y, mask, out, n);
}

// round 2
// speedup vs baseline: 1.4048x; 1.4048x over previous
#include <cuda_runtime.h>

// InterpolatorMask: out = valid ? sum_j mask[j] * y[(j + ind) % N] : 0
// Strategy: stream mask at HBM roofline with 4× uint4 loads per thread (MLP=4),
// integer OR-tree zero test, gather y only where mask != 0 (mask ~all zeros).

__global__ void im_init_out(float* __restrict__ out) {
    if (threadIdx.x == 0) out[0] = 0.0f;
}

#define TPB 256
#define V_PER_T 4   // uint4 loads per thread

__global__ void __launch_bounds__(TPB) im_kernel(
    const float* __restrict__ xp,
    const float* __restrict__ xOrig,
    const float* __restrict__ y,
    const float* __restrict__ mask,
    float* __restrict__ out,
    int n)
{
    const unsigned base = blockIdx.x * (TPB * V_PER_T) + threadIdx.x;  // uint4 index
    const uint4* __restrict__ mv = reinterpret_cast<const uint4*>(mask);

    // 4 independent, fully coalesced 16B streaming loads (front-batched -> MLP=4)
    uint4 a = __ldcs(&mv[base + 0 * TPB]);
    uint4 b = __ldcs(&mv[base + 1 * TPB]);
    uint4 c = __ldcs(&mv[base + 2 * TPB]);
    uint4 d = __ldcs(&mv[base + 3 * TPB]);

    const unsigned nz =
        (a.x | a.y | a.z | a.w) | (b.x | b.y | b.z | b.w) |
        (c.x | c.y | c.z | c.w) | (d.x | d.y | d.z | d.w);

    float sum = 0.0f;
    if (nz) {
        // Rare path: only threads holding nonzero mask words pay for this.
        const float x   = xp[0];
        const float x0  = xOrig[0];
        const float dx  = xOrig[1] - x0;
        const int   ind = (int)floorf((x - x0) / dx);

        #pragma unroll
        for (int v = 0; v < V_PER_T; v++) {
            uint4 m = (v == 0) ? a : (v == 1) ? b : (v == 2) ? c : d;
            const int e0 = (int)((base + v * TPB) * 4u);   // element index of m.x
            unsigned w[4] = {m.x, m.y, m.z, m.w};
            #pragma unroll
            for (int k = 0; k < 4; k++) {
                if (w[k] != 0u) {
                    int i = e0 + k + ind;
                    if (i >= n) i -= n;
                    sum += __uint_as_float(w[k]) * y[i];
                }
            }
        }
    }

    // Skip entirely-zero warps (the overwhelmingly common case).
    const unsigned act = __ballot_sync(0xffffffffu, sum != 0.0f);
    if (act != 0u) {
        #pragma unroll
        for (int o = 16; o > 0; o >>= 1)
            sum += __shfl_down_sync(0xffffffffu, sum, o);

        if ((threadIdx.x & 31u) == 0u && sum != 0.0f) {
            const float x    = xp[0];
            const float x0   = xOrig[0];
            const float xMax = xOrig[n - 1];
            if (x >= x0 && x < xMax) atomicAdd(out, sum);
        }
    }
}

extern "C" void kernel_launch(void* const* d_in, const int* in_sizes, int n_in,
                              void* d_out, int out_size)
{
    const float* x     = (const float*)d_in[0];
    const float* xOrig = (const float*)d_in[1];
    const float* y     = (const float*)d_in[2];
    const float* mask  = (const float*)d_in[3];
    float* out = (float*)d_out;

    const int n = in_sizes[1];                       // 16,777,216
    const int vec = n / 4;                           // uint4 count
    const int blocks = vec / (TPB * V_PER_T);        // 4096

    im_init_out<<<1, 32>>>(out);
    im_kernel<<<blocks, TPB>>>(x, xOrig, y, mask, out, n);
}

// round 3
// speedup vs baseline: 1.4090x; 1.0030x over previous
#include <cuda_runtime.h>

// InterpolatorMask: out = valid ? sum_j mask[j] * y[(j + ind) % N] : 0
// Single-kernel design: stream mask (64 MB) with 8x uint4 loads/thread,
// gather y only where mask != 0 (mask ~all zeros), accumulate rare nonzero
// warps into __device__ scratch via atomicAdd, last-finishing block finalizes
// (validity gate + write out + reset scratch -> deterministic per replay).

#define TPB 256
#define V_PER_T 8   // uint4 (16B) loads per thread -> 128 B/thread

__device__ float        g_acc  = 0.0f;
__device__ unsigned int g_done = 0u;

__global__ void __launch_bounds__(TPB) im_kernel(
    const float* __restrict__ xp,
    const float* __restrict__ xOrig,
    const float* __restrict__ y,
    const float* __restrict__ mask,
    float* __restrict__ out,
    int n)
{
    const unsigned base = blockIdx.x * (TPB * V_PER_T) + threadIdx.x;  // uint4 index
    const uint4* __restrict__ mv = reinterpret_cast<const uint4*>(mask);

    // 8 independent, fully coalesced 16B streaming loads (front-batched -> MLP=8)
    uint4 m[V_PER_T];
    #pragma unroll
    for (int v = 0; v < V_PER_T; v++)
        m[v] = __ldcs(&mv[base + v * TPB]);

    unsigned nz = 0u;
    #pragma unroll
    for (int v = 0; v < V_PER_T; v++)
        nz |= (m[v].x | m[v].y | m[v].z | m[v].w);

    float sum = 0.0f;
    if (nz) {
        // Rare path: only threads holding nonzero mask words pay for this.
        const float x   = xp[0];
        const float x0  = xOrig[0];
        const float dx  = xOrig[1] - x0;
        const int   ind = (int)floorf((x - x0) / dx);

        #pragma unroll
        for (int v = 0; v < V_PER_T; v++) {
            const int e0 = (int)((base + v * TPB) * 4u);   // element index of m[v].x
            unsigned w[4] = {m[v].x, m[v].y, m[v].z, m[v].w};
            #pragma unroll
            for (int k = 0; k < 4; k++) {
                if (w[k] != 0u) {
                    int i = e0 + k + ind;
                    if (i >= n) i -= n;
                    sum += __uint_as_float(w[k]) * y[i];
                }
            }
        }
    }

    // Skip entirely-zero warps (the overwhelmingly common case).
    const unsigned act = __ballot_sync(0xffffffffu, sum != 0.0f);
    if (act != 0u) {
        #pragma unroll
        for (int o = 16; o > 0; o >>= 1)
            sum += __shfl_down_sync(0xffffffffu, sum, o);
        if ((threadIdx.x & 31u) == 0u && sum != 0.0f)
            atomicAdd(&g_acc, sum);
    }

    // Last-block finalize: gate on validity, publish result, reset scratch.
    __syncthreads();
    if (threadIdx.x == 0) {
        __threadfence();
        const unsigned old = atomicAdd(&g_done, 1u);
        if (old == gridDim.x - 1u) {
            const float r    = *((volatile float*)&g_acc);
            const float x    = xp[0];
            const float x0   = xOrig[0];
            const float xMax = xOrig[n - 1];
            out[0] = (x >= x0 && x < xMax) ? r : 0.0f;
            // reset for next (deterministic) replay
            *((volatile float*)&g_acc)         = 0.0f;
            *((volatile unsigned int*)&g_done) = 0u;
        }
    }
}

extern "C" void kernel_launch(void* const* d_in, const int* in_sizes, int n_in,
                              void* d_out, int out_size)
{
    const float* x     = (const float*)d_in[0];
    const float* xOrig = (const float*)d_in[1];
    const float* y     = (const float*)d_in[2];
    const float* mask  = (const float*)d_in[3];
    float* out = (float*)d_out;

    const int n = in_sizes[1];                       // 16,777,216
    const int vec = n / 4;                           // uint4 count (4,194,304)
    const int blocks = vec / (TPB * V_PER_T);        // 2048

    im_kernel<<<blocks, TPB>>>(x, xOrig, y, mask, out, n);
}